// round 17
// baseline (speedup 1.0000x reference)
#include <cuda_runtime.h>
#include <cuda_fp16.h>
#include <math.h>
#include <stdint.h>

// ---------------- problem shapes ----------------
#define N_ROWS 8192
#define DIM    512
#define KPOS   8
#define NCLS   1000
#define C2     20.60992915555662f   // log2(e)/0.07

// ---------------- GEMM tiling ----------------
#define TMC 128                    // CTA M tile
#define TNC 128                    // CTA N tile
#define KCH 32                     // K halves per stage (two m16n8k16 sub-steps)
#define NKS (DIM / KCH)            // 16 k-steps -> 8 pairs
#define NB  (N_ROWS / 128)         // 64 blocks of 128 (triangular pairing)
#define NPAIRS (NB * (NB + 1) / 2) // 2080 CTAs
#define A_ST_BYTES (TMC * KCH * 2) // 8192
#define B_ST_BYTES (TNC * KCH * 2) // 8192
#define STAGE_BYTES (A_ST_BYTES + B_ST_BYTES)  // 16384
#define NSTAGES 6
#define DSM_BYTES (NSTAGES * STAGE_BYTES)      // 98304

#define RL_BLOCKS (N_ROWS / 4)     // 2048 rowloss blocks

// ---------------- scratch ----------------
__device__ __align__(16) __half g_qh[N_ROWS * DIM];  // fp16 Q, row-major
__device__ float g_posR[NB][N_ROWS];       // tile (bi,bj) row sums -> slot bj
__device__ float g_negR[NB][N_ROWS];
__device__ float g_posC[NB][N_ROWS];       // tile (bi,bj) col sums -> slot bi (bi!=bj)
__device__ float g_negC[NB][N_ROWS];
__device__ int   g_cnt[NCLS];
__device__ float g_invc[NCLS];
__device__ float g_loss[N_ROWS];
__device__ int   g_done = 0;               // rowloss completion counter (reset each run)

// ---------------- helpers ----------------
__device__ __forceinline__ uint32_t s2u(const void* p) {
    uint32_t a;
    asm("{ .reg .u64 t; cvta.to.shared.u64 t, %1; cvt.u32.u64 %0, t; }" : "=r"(a) : "l"(p));
    return a;
}
__device__ __forceinline__ void lds128(uint32_t* r, uint32_t a) {
    asm volatile("ld.shared.v4.b32 {%0,%1,%2,%3}, [%4];"
                 : "=r"(r[0]), "=r"(r[1]), "=r"(r[2]), "=r"(r[3]) : "r"(a));
}
__device__ __forceinline__ void cpasync16(uint32_t dst, const void* src) {
    asm volatile("cp.async.cg.shared.global [%0], [%1], 16;" :: "r"(dst), "l"(src) : "memory");
}
__device__ __forceinline__ void cp_commit() {
    asm volatile("cp.async.commit_group;" ::: "memory");
}
__device__ __forceinline__ float ex2f(float x) {
    float r;
    asm("ex2.approx.ftz.f32 %0, %1;" : "=f"(r) : "f"(x));
    return r;
}
// fp16 mma, fp32 accum. k-slot permutation: sub-mma uses contiguous 16B row chunks.
#define MMA_F16(c, a0, a1, a2, a3, b0, b1)                                    \
    asm volatile(                                                             \
        "mma.sync.aligned.m16n8k16.row.col.f32.f16.f16.f32 "                  \
        "{%0,%1,%2,%3},{%4,%5,%6,%7},{%8,%9},{%0,%1,%2,%3};"                  \
        : "+f"(c[0]), "+f"(c[1]), "+f"(c[2]), "+f"(c[3])                      \
        : "r"(a0), "r"(a1), "r"(a2), "r"(a3), "r"(b0), "r"(b1))

// ---------------- kernel 1: fp16-convert Q (32 floats/thread) + fused bincount ----------------
__global__ void k_prep(const float* __restrict__ q, const int* __restrict__ y) {
    if (blockIdx.x == 0) {
        __shared__ int sc[NCLS];
        for (int c = threadIdx.x; c < NCLS; c += blockDim.x) sc[c] = 0;
        __syncthreads();
        for (int i = threadIdx.x; i < N_ROWS; i += blockDim.x)
            atomicAdd(&sc[y[i]], 1);
        __syncthreads();
        for (int c = threadIdx.x; c < NCLS; c += blockDim.x) {
            int v = sc[c];
            g_cnt[c]  = v;
            g_invc[c] = v > 0 ? 1.0f / (float)v : 0.0f;
        }
    }
    int gid = blockIdx.x * blockDim.x + threadIdx.x;   // 32 floats each
    const float4* q4 = (const float4*)q;
    // issue all 8 loads first (MLP), then convert+store
    float4 v[8];
#pragma unroll
    for (int j = 0; j < 8; ++j) v[j] = q4[gid * 8 + j];
#pragma unroll
    for (int j = 0; j < 4; ++j) {
        __half2 h0 = __float22half2_rn(make_float2(v[2 * j].x,     v[2 * j].y));
        __half2 h1 = __float22half2_rn(make_float2(v[2 * j].z,     v[2 * j].w));
        __half2 h2 = __float22half2_rn(make_float2(v[2 * j + 1].x, v[2 * j + 1].y));
        __half2 h3 = __float22half2_rn(make_float2(v[2 * j + 1].z, v[2 * j + 1].w));
        uint4 o;
        o.x = *(uint32_t*)&h0; o.y = *(uint32_t*)&h1;
        o.z = *(uint32_t*)&h2; o.w = *(uint32_t*)&h3;
        ((uint4*)g_qh)[gid * 4 + j] = o;
    }
}

// ---------------- kernel 2: triangular fp16 mma Gram + two-sided epilogue ----------------
// Pair (bi, bj), bi<=bj over 64 blocks of 128. CTA tile: rows [bi*128, +128),
// cols [bj*128, +128). Row sums -> slot bj; col sums -> slot bi (bi!=bj).
// 8 warps = 4(M) x 2(N), warp tile 32x64. 2 CTAs/SM. 6-stage pipe, barrier per step-pair.
__global__ __launch_bounds__(256, 2)
void k_gram(const int* __restrict__ y) {
    extern __shared__ __align__(16) char dsm_raw[];
    __shared__ int   ysh[TNC];
    __shared__ float wsh[TNC];
    __shared__ float spos[2][TMC];
    __shared__ float sneg[2][TMC];
    __shared__ float scolP[4][TNC];
    __shared__ float scolN[4][TNC];

    const int tid  = threadIdx.x;
    const int warp = tid >> 5;
    const int lane = tid & 31;
    const int g = lane >> 2;          // group id (row within 8)
    const int t = lane & 3;           // thread-in-group (16B row chunk)
    const int wm = warp >> 1;         // warp M index (0..3)
    const int wn = warp & 1;          // warp N index (0..1)

    // ---- decode triangular pair ----
    int bi = 0, rem = blockIdx.x;
    while (rem >= (NB - bi)) { rem -= (NB - bi); ++bi; }
    const int bj = bi + rem;
    const int i0 = bi * TMC;
    const int j0 = bj * TNC;
    const bool do_col = (bi != bj);

    const uint32_t dsm = s2u(dsm_raw);

    // column labels/weights
    if (tid < TNC) {
        int yy = y[j0 + tid];
        ysh[tid] = yy;
        wsh[tid] = g_invc[yy];
    }

    // ---- per-thread copy descriptors (4 x 16B per stage) ----
    const char* srcp[4];
    uint32_t    sdst[4];
#pragma unroll
    for (int j = 0; j < 4; ++j) {
        int u   = tid + 256 * j;      // 16B unit index 0..1023
        int row = u >> 2;             // 0..255
        int tt  = u & 3;
        int lr, grow; uint32_t base;
        if (row < TMC) { lr = row;        grow = i0 + lr; base = 0; }
        else           { lr = row - TMC;  grow = j0 + lr; base = A_ST_BYTES; }
        srcp[j] = (const char*)(g_qh + (size_t)grow * DIM) + tt * 16;
        sdst[j] = base + (uint32_t)lr * 64 + (uint32_t)((tt ^ ((lr >> 1) & 3)) * 16);
    }

    // ---- per-thread fragment read offsets (64B rows) ----
    uint32_t Aoff[2][2], Boff[8];
#pragma unroll
    for (int mt = 0; mt < 2; ++mt) {
#pragma unroll
        for (int hh = 0; hh < 2; ++hh) {
            int r = wm * 32 + mt * 16 + hh * 8 + g;
            Aoff[mt][hh] = (uint32_t)r * 64 + (uint32_t)((t ^ ((r >> 1) & 3)) * 16);
        }
    }
#pragma unroll
    for (int nt = 0; nt < 8; ++nt) {
        int r = wn * 64 + nt * 8 + g;
        Boff[nt] = A_ST_BYTES + (uint32_t)r * 64 + (uint32_t)((t ^ ((r >> 1) & 3)) * 16);
    }

    float c[2][8][4];
#pragma unroll
    for (int mt = 0; mt < 2; ++mt)
#pragma unroll
        for (int nt = 0; nt < 8; ++nt)
#pragma unroll
            for (int e = 0; e < 4; ++e) c[mt][nt][e] = 0.0f;

    // ---- prologue: pairs 0,1 (stages 0..3) ----
#pragma unroll
    for (int pp = 0; pp < 2; ++pp) {
#pragma unroll
        for (int h = 0; h < 2; ++h) {
            int s = 2 * pp + h;
            uint32_t sb = dsm + s * STAGE_BYTES;
#pragma unroll
            for (int j = 0; j < 4; ++j) cpasync16(sb + sdst[j], srcp[j] + s * 64);
        }
        cp_commit();
    }

    // ---- main loop: 8 step-pairs, one barrier each ----
    int b0 = 0;   // buffer index of first stage of this pair
#pragma unroll 1
    for (int p = 0; p < NKS / 2; ++p) {
        if (p < NKS / 2 - 1) asm volatile("cp.async.wait_group 1;" ::: "memory");
        else                 asm volatile("cp.async.wait_group 0;" ::: "memory");
        __syncthreads();

        if (p + 2 < NKS / 2) {
            int pb = b0 + 4; if (pb >= NSTAGES) pb -= NSTAGES;
            int s0 = 2 * (p + 2);
#pragma unroll
            for (int h = 0; h < 2; ++h) {
                uint32_t sb = dsm + (pb + h) * STAGE_BYTES;
#pragma unroll
                for (int j = 0; j < 4; ++j) cpasync16(sb + sdst[j], srcp[j] + (s0 + h) * 64);
            }
            cp_commit();
        }

#pragma unroll
        for (int h = 0; h < 2; ++h) {
            uint32_t sb = dsm + (b0 + h) * STAGE_BYTES;
            uint32_t a[2][8];
#pragma unroll
            for (int mt = 0; mt < 2; ++mt) {
                lds128(&a[mt][0], sb + Aoff[mt][0]);   // row g:   halves 8t..8t+7
                lds128(&a[mt][4], sb + Aoff[mt][1]);   // row g+8
            }
            uint32_t bb[2][4];
            lds128(bb[0], sb + Boff[0]);
#pragma unroll
            for (int nt = 0; nt < 8; ++nt) {
                if (nt < 7) lds128(bb[(nt + 1) & 1], sb + Boff[nt + 1]);
                uint32_t* bv = bb[nt & 1];
#pragma unroll
                for (int mt = 0; mt < 2; ++mt) {
                    MMA_F16(c[mt][nt], a[mt][0], a[mt][4], a[mt][1], a[mt][5], bv[0], bv[1]);
                    MMA_F16(c[mt][nt], a[mt][2], a[mt][6], a[mt][3], a[mt][7], bv[2], bv[3]);
                }
            }
        }
        b0 += 2; if (b0 >= NSTAGES) b0 = 0;
    }

    // ---- fused two-sided epilogue ----
    int   yrow[4];
    float winv[4];
#pragma unroll
    for (int mt = 0; mt < 2; ++mt)
#pragma unroll
        for (int hh = 0; hh < 2; ++hh) {
            int yy = y[i0 + wm * 32 + mt * 16 + hh * 8 + g];
            yrow[mt * 2 + hh] = yy;
            winv[mt * 2 + hh] = g_invc[yy];
        }

    float pos[4], neg[4];
    float colp[16], coln[16];
#pragma unroll
    for (int e = 0; e < 4; ++e)  { pos[e] = 0.0f;  neg[e] = 0.0f; }
#pragma unroll
    for (int e = 0; e < 16; ++e) { colp[e] = 0.0f; coln[e] = 0.0f; }

#pragma unroll
    for (int mt = 0; mt < 2; ++mt) {
        const int gr0 = i0 + wm * 32 + mt * 16 + g;     // rows for c0/c1
        const int gr1 = gr0 + 8;                        // rows for c2/c3
#pragma unroll
        for (int nt = 0; nt < 8; ++nt) {
            const int cl = wn * 64 + nt * 8 + 2 * t;
#pragma unroll
            for (int e = 0; e < 4; ++e) {
                const int col  = cl + (e & 1);
                const int grow = (e < 2) ? gr0 : gr1;
                const int idx  = mt * 2 + (e >> 1);
                const int ci   = nt * 2 + (e & 1);
                float d = c[mt][nt][e];
                float ev = ex2f(d * C2);
                bool nz   = (d != 0.0f);
                bool same = (ysh[col] == yrow[idx]);
                bool slf  = (j0 + col == grow);
                if (nz & same & !slf) pos[idx] += ev;
                if (nz & !same)       neg[idx] += ev * wsh[col];
                // transposed contribution (rows of bj get sums over this CTA's rows)
                if (nz & same)        colp[ci] += ev;
                if (nz & !same)       coln[ci] += ev * winv[idx];
            }
        }
    }

    // row reduce over the 4 lanes of each group (t axis)
#pragma unroll
    for (int e = 0; e < 4; ++e) {
        pos[e] += __shfl_xor_sync(0xffffffffu, pos[e], 1);
        pos[e] += __shfl_xor_sync(0xffffffffu, pos[e], 2);
        neg[e] += __shfl_xor_sync(0xffffffffu, neg[e], 1);
        neg[e] += __shfl_xor_sync(0xffffffffu, neg[e], 2);
    }
    if (t == 0) {
#pragma unroll
        for (int mt = 0; mt < 2; ++mt)
#pragma unroll
            for (int hh = 0; hh < 2; ++hh) {
                int r = wm * 32 + mt * 16 + hh * 8 + g;
                spos[wn][r] = pos[mt * 2 + hh];
                sneg[wn][r] = neg[mt * 2 + hh];
            }
    }

    // col reduce over the 8 groups (g axis)
#pragma unroll
    for (int e = 0; e < 16; ++e) {
        colp[e] += __shfl_xor_sync(0xffffffffu, colp[e], 4);
        colp[e] += __shfl_xor_sync(0xffffffffu, colp[e], 8);
        colp[e] += __shfl_xor_sync(0xffffffffu, colp[e], 16);
        coln[e] += __shfl_xor_sync(0xffffffffu, coln[e], 4);
        coln[e] += __shfl_xor_sync(0xffffffffu, coln[e], 8);
        coln[e] += __shfl_xor_sync(0xffffffffu, coln[e], 16);
    }
    if (g == 0) {  // lanes t=0..3 hold full g-sums
#pragma unroll
        for (int nt = 0; nt < 8; ++nt)
#pragma unroll
            for (int e01 = 0; e01 < 2; ++e01) {
                int col = wn * 64 + nt * 8 + 2 * t + e01;
                scolP[wm][col] = colp[nt * 2 + e01];
                scolN[wm][col] = coln[nt * 2 + e01];
            }
    }
    __syncthreads();
    if (tid < TMC) {
        float pp = spos[0][tid] + spos[1][tid];
        float nn = sneg[0][tid] + sneg[1][tid];
        g_posR[bj][i0 + tid] = pp;
        g_negR[bj][i0 + tid] = nn;
    }
    if (do_col && tid < TNC) {
        float pp = (scolP[0][tid] + scolP[1][tid]) + (scolP[2][tid] + scolP[3][tid]);
        float nn = (scolN[0][tid] + scolN[1][tid]) + (scolN[2][tid] + scolN[3][tid]);
        g_posC[bi][j0 + tid] = pp;
        g_negC[bi][j0 + tid] = nn;
    }
}

// ---------------- kernel 3: k-positive sims + per-row loss + fused final mean ----------------
// 2 warps per row: warp half h handles kk in [4h, 4h+4). Slot-gather loads issued
// up-front. Last block (global counter) computes the final mean in fixed order.
__global__ __launch_bounds__(256)
void k_rowloss(const float* __restrict__ q,
               const float* __restrict__ kv,
               const int* __restrict__ y,
               float* __restrict__ out) {
    __shared__ float sesum[8];
    __shared__ int   s_last;
    const int warp = threadIdx.x >> 5;
    const int lane = threadIdx.x & 31;
    const int rloc = warp >> 1;          // 0..3
    const int half = warp & 1;
    const int i = blockIdx.x * 4 + rloc;

    // early-issue slot gather (half 0 warps): 64 slots, 2 per lane, fixed order
    const int b = i >> 7;
    const int nR = NB - b;
    float ptg[2] = {0.0f, 0.0f}, ntg[2] = {0.0f, 0.0f};
    if (half == 0) {
#pragma unroll
        for (int hh = 0; hh < 2; ++hh) {
            int s = lane + 32 * hh;
            if (s < nR) { ptg[hh] = g_posR[b + s][i];   ntg[hh] = g_negR[b + s][i]; }
            else        { ptg[hh] = g_posC[s - nR][i];  ntg[hh] = g_negC[s - nR][i]; }
        }
    }

    const float4* qi = (const float4*)(q + (size_t)i * DIM);
    float4 qreg[4];
#pragma unroll
    for (int e = 0; e < 4; ++e) qreg[e] = qi[lane + 32 * e];

    // one batch: 16 streaming float4 loads in flight per thread
    float4 bld[4][4];
#pragma unroll
    for (int k4 = 0; k4 < 4; ++k4) {
        const float4* kp = (const float4*)(kv + ((size_t)i * KPOS + half * 4 + k4) * DIM);
#pragma unroll
        for (int e = 0; e < 4; ++e) bld[k4][e] = __ldcs(kp + lane + 32 * e);
    }
    float acc[4] = {0.0f, 0.0f, 0.0f, 0.0f};
#pragma unroll
    for (int k4 = 0; k4 < 4; ++k4)
#pragma unroll
        for (int e = 0; e < 4; ++e) {
            acc[k4] = fmaf(qreg[e].x, bld[k4][e].x, acc[k4]);
            acc[k4] = fmaf(qreg[e].y, bld[k4][e].y, acc[k4]);
            acc[k4] = fmaf(qreg[e].z, bld[k4][e].z, acc[k4]);
            acc[k4] = fmaf(qreg[e].w, bld[k4][e].w, acc[k4]);
        }
    float esum = 0.0f;
#pragma unroll
    for (int k4 = 0; k4 < 4; ++k4) {
#pragma unroll
        for (int off = 16; off > 0; off >>= 1)
            acc[k4] += __shfl_down_sync(0xffffffffu, acc[k4], off);
        if (lane == 0) esum += ex2f(acc[k4] * C2);
    }
    if (lane == 0) sesum[warp] = esum;
    __syncthreads();

    if (half == 0) {
        float pt = ptg[0] + ptg[1];
        float nt = ntg[0] + ntg[1];
#pragma unroll
        for (int off = 16; off > 0; off >>= 1) {
            pt += __shfl_down_sync(0xffffffffu, pt, off);
            nt += __shfl_down_sync(0xffffffffu, nt, off);
        }
        if (lane == 0) {
            pt += sesum[2 * rloc] + sesum[2 * rloc + 1];
            float num = logf(pt);
            float den = logf(nt);
            float cnt = (float)(g_cnt[y[i]] - 1 + KPOS);
            g_loss[i] = -(num - den) / cnt;
            __threadfence();                   // make this row's loss globally visible
        }
    }
    __syncthreads();

    // ---- last-block final mean (deterministic fixed-order sum) ----
    if (threadIdx.x == 0) {
        int v = atomicAdd(&g_done, 1);
        s_last = (v == RL_BLOCKS - 1) ? 1 : 0;
    }
    __syncthreads();
    if (s_last) {
        __threadfence();                       // acquire all g_loss writes
        __shared__ float sm[256];
        const float4* l4 = (const float4*)g_loss;
        float s = 0.0f;
#pragma unroll
        for (int j = 0; j < 8; ++j) {          // 32 floats per thread, fixed order
            float4 v4 = l4[threadIdx.x * 8 + j];
            s += ((v4.x + v4.y) + (v4.z + v4.w));
        }
        sm[threadIdx.x] = s;
        __syncthreads();
        for (int st = 128; st > 0; st >>= 1) {
            if (threadIdx.x < st) sm[threadIdx.x] += sm[threadIdx.x + st];
            __syncthreads();
        }
        if (threadIdx.x == 0) {
            out[0] = sm[0] * (1.0f / (float)N_ROWS);
            g_done = 0;                        // reset for next graph replay
        }
    }
}

// ---------------- launch ----------------
extern "C" void kernel_launch(void* const* d_in, const int* in_sizes, int n_in,
                              void* d_out, int out_size) {
    const float* q  = nullptr;
    const float* kv = nullptr;
    const int*   y  = nullptr;
    for (int i = 0; i < n_in; ++i) {
        long long sz = in_sizes[i];
        if (sz == (long long)N_ROWS * DIM)             q  = (const float*)d_in[i];
        else if (sz == (long long)N_ROWS * KPOS * DIM) kv = (const float*)d_in[i];
        else if (sz == (long long)N_ROWS)              y  = (const int*)d_in[i];
    }
    float* out = (float*)d_out;

    cudaFuncSetAttribute(k_gram, cudaFuncAttributeMaxDynamicSharedMemorySize, DSM_BYTES);

    k_prep<<<(N_ROWS * DIM / 32) / 256, 256>>>(q, y);
    k_gram<<<NPAIRS, 256, DSM_BYTES>>>(y);
    k_rowloss<<<RL_BLOCKS, 256>>>(q, kv, y, out);
}